// round 1
// baseline (speedup 1.0000x reference)
#include <cuda_runtime.h>
#include <math.h>

#define NN  65536
#define EE  524288
#define DHD 64
#define NH  4
#define HD  16

// ---------------- scratch (static device globals; no runtime alloc) ----------------
__device__ float g_q[NN * DHD];       // q projections            [N,64]
__device__ float g_k[NN * DHD];       // rotated k (edge_w)       [N,64]
__device__ float g_v[NN * DHD];       // rotated v (msg_w)        [N,64]
__device__ float g_attn[NN * DHD];    // attention output         [N,64]
__device__ float g_score[EE * NH];    // per-edge scores          [E,4]
__device__ int   g_cnt[NN];
__device__ int   g_cur[NN];
__device__ int   g_rs[NN + 1];        // CSR row starts (by dst)
__device__ int   g_elist[EE];         // CSR edge ids

// ---------------- CSR build ----------------
__global__ void k_zero_cnt() {
    int i = blockIdx.x * blockDim.x + threadIdx.x;
    if (i < NN) g_cnt[i] = 0;
}

__global__ void k_count(const int* __restrict__ ei) {
    int e = blockIdx.x * blockDim.x + threadIdx.x;
    if (e < EE) atomicAdd(&g_cnt[ei[EE + e]], 1);
}

__global__ void k_scan() {
    __shared__ int sb[1024];
    int t = threadIdx.x;
    int base = t * 64;
    int s = 0;
    for (int j = 0; j < 64; j++) s += g_cnt[base + j];
    sb[t] = s;
    __syncthreads();
    for (int off = 1; off < 1024; off <<= 1) {
        int v = (t >= off) ? sb[t - off] : 0;
        __syncthreads();
        sb[t] += v;
        __syncthreads();
    }
    int run = sb[t] - s;  // exclusive prefix of this thread's chunk
    for (int j = 0; j < 64; j++) {
        g_rs[base + j]  = run;
        g_cur[base + j] = run;
        run += g_cnt[base + j];
    }
    if (t == 1023) g_rs[NN] = run;
}

__global__ void k_scatter(const int* __restrict__ ei) {
    int e = blockIdx.x * blockDim.x + threadIdx.x;
    if (e < EE) {
        int d = ei[EE + e];
        int p = atomicAdd(&g_cur[d], 1);
        g_elist[p] = e;
    }
}

// ---------------- K1: node LN + QKV projection + head rotations ----------------
// thread-per-node, weights in smem (uniform-address broadcast reads)
#define B1 256
__global__ __launch_bounds__(B1) void k_node_proj(
    const float* __restrict__ x,
    const float* __restrict__ Wq, const float* __restrict__ bq,
    const float* __restrict__ Wk, const float* __restrict__ bk,
    const float* __restrict__ Wv, const float* __restrict__ bv,
    const float* __restrict__ edge_w, const float* __restrict__ msg_w,
    const float* __restrict__ ln1g, const float* __restrict__ ln1b)
{
    extern __shared__ float sm[];
    float* sWq = sm;               // 4096
    float* sWk = sWq + 4096;       // 4096
    float* sWv = sWk + 4096;       // 4096
    float* sEW = sWv + 4096;       // 1024
    float* sMW = sEW + 1024;       // 1024
    float* sB  = sMW + 1024;       // bq,bk,bv,ln1g,ln1b : 5*64
    float* tile = sB + 320;        // B1*65

    int t = threadIdx.x;
    for (int i = t; i < 4096; i += B1) { sWq[i] = Wq[i]; sWk[i] = Wk[i]; sWv[i] = Wv[i]; }
    for (int i = t; i < 1024; i += B1) { sEW[i] = edge_w[i]; sMW[i] = msg_w[i]; }
    if (t < 64) { sB[t] = bq[t]; sB[64+t] = bk[t]; sB[128+t] = bv[t]; sB[192+t] = ln1g[t]; sB[256+t] = ln1b[t]; }
    int nb = blockIdx.x * B1;
    for (int i = t; i < B1 * 64; i += B1) {
        int r = i >> 6, c = i & 63;
        tile[r * 65 + c] = x[(nb + r) * 64 + c];
    }
    __syncthreads();

    float* row = &tile[t * 65];
    // LayerNorm
    float s = 0.f;
    #pragma unroll
    for (int d = 0; d < 64; d++) s += row[d];
    float mu = s * (1.0f / 64.0f);
    float var = 0.f;
    #pragma unroll
    for (int d = 0; d < 64; d++) { float a = row[d] - mu; var += a * a; }
    float inv = 1.0f / sqrtf(var * (1.0f / 64.0f) + 1e-5f);
    #pragma unroll
    for (int d = 0; d < 64; d++) row[d] = (row[d] - mu) * inv * sB[192 + d] + sB[256 + d];

    int n = nb + t;
    float acc[64];

    // ---- Q ----
    #pragma unroll
    for (int c = 0; c < 64; c++) acc[c] = sB[c];
    #pragma unroll 4
    for (int d = 0; d < 64; d++) {
        float a = row[d];
        const float4* w = (const float4*)&sWq[d * 64];
        #pragma unroll
        for (int c4 = 0; c4 < 16; c4++) {
            float4 ww = w[c4];
            acc[c4*4+0] += a * ww.x; acc[c4*4+1] += a * ww.y;
            acc[c4*4+2] += a * ww.z; acc[c4*4+3] += a * ww.w;
        }
    }
    {
        float4* o = (float4*)&g_q[n * 64];
        #pragma unroll
        for (int c4 = 0; c4 < 16; c4++) o[c4] = make_float4(acc[c4*4], acc[c4*4+1], acc[c4*4+2], acc[c4*4+3]);
    }

    // ---- K (then rotate with edge_w) ----
    #pragma unroll
    for (int c = 0; c < 64; c++) acc[c] = sB[64 + c];
    #pragma unroll 4
    for (int d = 0; d < 64; d++) {
        float a = row[d];
        const float4* w = (const float4*)&sWk[d * 64];
        #pragma unroll
        for (int c4 = 0; c4 < 16; c4++) {
            float4 ww = w[c4];
            acc[c4*4+0] += a * ww.x; acc[c4*4+1] += a * ww.y;
            acc[c4*4+2] += a * ww.z; acc[c4*4+3] += a * ww.w;
        }
    }
    #pragma unroll
    for (int h = 0; h < NH; h++) {
        float r0[16];
        #pragma unroll
        for (int c = 0; c < 16; c++) {
            float su = 0.f;
            #pragma unroll
            for (int d2 = 0; d2 < 16; d2++) su += acc[h*16 + d2] * sEW[h*256 + d2*16 + c];
            r0[c] = su;
        }
        float4* o = (float4*)&g_k[n * 64 + h * 16];
        #pragma unroll
        for (int c4 = 0; c4 < 4; c4++) o[c4] = make_float4(r0[c4*4], r0[c4*4+1], r0[c4*4+2], r0[c4*4+3]);
    }

    // ---- V (then rotate with msg_w) ----
    #pragma unroll
    for (int c = 0; c < 64; c++) acc[c] = sB[128 + c];
    #pragma unroll 4
    for (int d = 0; d < 64; d++) {
        float a = row[d];
        const float4* w = (const float4*)&sWv[d * 64];
        #pragma unroll
        for (int c4 = 0; c4 < 16; c4++) {
            float4 ww = w[c4];
            acc[c4*4+0] += a * ww.x; acc[c4*4+1] += a * ww.y;
            acc[c4*4+2] += a * ww.z; acc[c4*4+3] += a * ww.w;
        }
    }
    #pragma unroll
    for (int h = 0; h < NH; h++) {
        float r0[16];
        #pragma unroll
        for (int c = 0; c < 16; c++) {
            float su = 0.f;
            #pragma unroll
            for (int d2 = 0; d2 < 16; d2++) su += acc[h*16 + d2] * sMW[h*256 + d2*16 + c];
            r0[c] = su;
        }
        float4* o = (float4*)&g_v[n * 64 + h * 16];
        #pragma unroll
        for (int c4 = 0; c4 < 4; c4++) o[c4] = make_float4(r0[c4*4], r0[c4*4+1], r0[c4*4+2], r0[c4*4+3]);
    }
}

// ---------------- K2: per-edge LN + e projection + scores ----------------
#define B2 256
__global__ __launch_bounds__(B2) void k_edge(
    const float* __restrict__ ea,
    const int*   __restrict__ ei,
    const float* __restrict__ We, const float* __restrict__ be,
    const float* __restrict__ lneg, const float* __restrict__ lneb,
    const float* __restrict__ attn_bi)
{
    extern __shared__ float sm[];
    float* sW = sm;            // 4096
    float* sS = sW + 4096;     // be(64), g(64), b(64)
    float* tile = sS + 192;    // B2*65

    int t = threadIdx.x;
    for (int i = t; i < 4096; i += B2) sW[i] = We[i];
    if (t < 64) { sS[t] = be[t]; sS[64 + t] = lneg[t]; sS[128 + t] = lneb[t]; }
    int eb = blockIdx.x * B2;
    for (int i = t; i < B2 * 64; i += B2) {
        int r = i >> 6, c = i & 63;
        tile[r * 65 + c] = ea[(eb + r) * 64 + c];
    }
    __syncthreads();

    float* row = &tile[t * 65];
    float s = 0.f;
    #pragma unroll
    for (int d = 0; d < 64; d++) s += row[d];
    float mu = s * (1.0f / 64.0f);
    float var = 0.f;
    #pragma unroll
    for (int d = 0; d < 64; d++) { float a = row[d] - mu; var += a * a; }
    float inv = 1.0f / sqrtf(var * (1.0f / 64.0f) + 1e-5f);
    #pragma unroll
    for (int d = 0; d < 64; d++) row[d] = (row[d] - mu) * inv * sS[64 + d] + sS[128 + d];

    // e = ea_ln @ We + be
    float acc[64];
    #pragma unroll
    for (int c = 0; c < 64; c++) acc[c] = sS[c];
    #pragma unroll 4
    for (int d = 0; d < 64; d++) {
        float a = row[d];
        const float4* w = (const float4*)&sW[d * 64];
        #pragma unroll
        for (int c4 = 0; c4 < 16; c4++) {
            float4 ww = w[c4];
            acc[c4*4+0] += a * ww.x; acc[c4*4+1] += a * ww.y;
            acc[c4*4+2] += a * ww.z; acc[c4*4+3] += a * ww.w;
        }
    }

    int e   = eb + t;
    int src = ei[e];
    int dst = ei[EE + e];
    float sc[4];
    #pragma unroll
    for (int h = 0; h < NH; h++) {
        const float4* qp = (const float4*)&g_q[dst * 64 + h * 16];
        const float4* kp = (const float4*)&g_k[src * 64 + h * 16];
        float dot = 0.f;
        #pragma unroll
        for (int i4 = 0; i4 < 4; i4++) {
            float4 q4 = qp[i4];
            float4 k4 = kp[i4];
            int cb = h * 16 + i4 * 4;
            dot += q4.x * k4.x * acc[cb+0];
            dot += q4.y * k4.y * acc[cb+1];
            dot += q4.z * k4.z * acc[cb+2];
            dot += q4.w * k4.w * acc[cb+3];
        }
        sc[h] = dot * 0.25f + attn_bi[h * 2];  // scale=1/sqrt(16), attn_bi[:,0]
    }
    ((float4*)&g_score[e * 4])[0] = make_float4(sc[0], sc[1], sc[2], sc[3]);
}

// ---------------- K3: per-dst-node segment softmax + weighted gather ----------------
__global__ __launch_bounds__(256) void k_attn(const int* __restrict__ ei)
{
    int gw   = (blockIdx.x * blockDim.x + threadIdx.x) >> 5;
    int lane = threadIdx.x & 31;
    if (gw >= NN) return;
    int start = g_rs[gw], end = g_rs[gw + 1];

    const float NEG = __int_as_float(0xff800000);  // -inf
    float m0 = NEG, m1 = NEG, m2 = NEG, m3 = NEG;
    for (int i = start + lane; i < end; i += 32) {
        float4 sc = ((const float4*)&g_score[g_elist[i] * 4])[0];
        m0 = fmaxf(m0, sc.x); m1 = fmaxf(m1, sc.y);
        m2 = fmaxf(m2, sc.z); m3 = fmaxf(m3, sc.w);
    }
    #pragma unroll
    for (int o = 16; o; o >>= 1) {
        m0 = fmaxf(m0, __shfl_xor_sync(0xffffffffu, m0, o));
        m1 = fmaxf(m1, __shfl_xor_sync(0xffffffffu, m1, o));
        m2 = fmaxf(m2, __shfl_xor_sync(0xffffffffu, m2, o));
        m3 = fmaxf(m3, __shfl_xor_sync(0xffffffffu, m3, o));
    }
    float s0 = 0.f, s1 = 0.f, s2 = 0.f, s3 = 0.f;
    for (int i = start + lane; i < end; i += 32) {
        float4 sc = ((const float4*)&g_score[g_elist[i] * 4])[0];
        s0 += __expf(sc.x - m0); s1 += __expf(sc.y - m1);
        s2 += __expf(sc.z - m2); s3 += __expf(sc.w - m3);
    }
    #pragma unroll
    for (int o = 16; o; o >>= 1) {
        s0 += __shfl_xor_sync(0xffffffffu, s0, o);
        s1 += __shfl_xor_sync(0xffffffffu, s1, o);
        s2 += __shfl_xor_sync(0xffffffffu, s2, o);
        s3 += __shfl_xor_sync(0xffffffffu, s3, o);
    }

    int   h0  = lane >> 4;                  // head of dim `lane`; dim lane+32 is head h0+2
    float mh0 = h0 ? m1 : m0;
    float mh1 = h0 ? m3 : m2;
    float a0 = 0.f, a1 = 0.f;
    for (int i = start; i < end; i++) {     // serial over ~8 edges, broadcast loads
        int e   = g_elist[i];
        int src = ei[e];
        float w0 = __expf(g_score[e * 4 + h0]     - mh0);
        float w1 = __expf(g_score[e * 4 + 2 + h0] - mh1);
        a0 += w0 * g_v[src * 64 + lane];
        a1 += w1 * g_v[src * 64 + 32 + lane];
    }
    float d0 = (h0 ? s1 : s0) + 1e-16f;
    float d1 = (h0 ? s3 : s2) + 1e-16f;
    g_attn[gw * 64 + lane]      = a0 / d0;
    g_attn[gw * 64 + 32 + lane] = a1 / d1;
}

// ---------------- K4: Wo + gated residual + FFN ----------------
#define B4 256
__global__ __launch_bounds__(B4) void k_final(
    const float* __restrict__ x,
    const float* __restrict__ Wo, const float* __restrict__ bo,
    const float* __restrict__ skip,
    const float* __restrict__ ln2g, const float* __restrict__ ln2b,
    const float* __restrict__ W1, const float* __restrict__ b1,
    const float* __restrict__ W2, const float* __restrict__ b2,
    float* __restrict__ out)
{
    extern __shared__ float sm[];
    float* sWo = sm;               // 4096
    float* sW1 = sWo + 4096;       // 8192
    float* sW2 = sW1 + 8192;       // 8192
    float* sS  = sW2 + 8192;       // bo(64), b1(128), b2(64), g(64), b(64) = 384
    float* tA  = sS + 384;         // B4*65
    float* tB  = tA + B4 * 65;     // B4*65

    int t = threadIdx.x;
    for (int i = t; i < 4096; i += B4) sWo[i] = Wo[i];
    for (int i = t; i < 8192; i += B4) { sW1[i] = W1[i]; sW2[i] = W2[i]; }
    if (t < 64)  { sS[t] = bo[t]; sS[192 + t] = b2[t]; sS[256 + t] = ln2g[t]; sS[320 + t] = ln2b[t]; }
    if (t < 128) sS[64 + t] = b1[t];
    int nb = blockIdx.x * B4;
    for (int i = t; i < B4 * 64; i += B4) {
        int r = i >> 6, c = i & 63;
        tA[r * 65 + c] = g_attn[(nb + r) * 64 + c];
    }
    __syncthreads();

    int n = nb + t;
    float* rA = &tA[t * 65];
    float* rB = &tB[t * 65];

    // o = attn @ Wo + bo
    float acc[64];
    #pragma unroll
    for (int c = 0; c < 64; c++) acc[c] = sS[c];
    #pragma unroll 4
    for (int d = 0; d < 64; d++) {
        float a = rA[d];
        const float4* w = (const float4*)&sWo[d * 64];
        #pragma unroll
        for (int c4 = 0; c4 < 16; c4++) {
            float4 ww = w[c4];
            acc[c4*4+0] += a * ww.x; acc[c4*4+1] += a * ww.y;
            acc[c4*4+2] += a * ww.z; acc[c4*4+3] += a * ww.w;
        }
    }

    // gated residual: h1 = g*o + (1-g)*x
    float gg = 1.0f / (1.0f + __expf(-skip[0]));
    const float4* xp = (const float4*)&x[n * 64];
    #pragma unroll
    for (int c4 = 0; c4 < 16; c4++) {
        float4 xx = xp[c4];
        acc[c4*4+0] = gg * acc[c4*4+0] + (1.0f - gg) * xx.x;
        acc[c4*4+1] = gg * acc[c4*4+1] + (1.0f - gg) * xx.y;
        acc[c4*4+2] = gg * acc[c4*4+2] + (1.0f - gg) * xx.z;
        acc[c4*4+3] = gg * acc[c4*4+3] + (1.0f - gg) * xx.w;
    }

    // LN(h1) -> rB
    float s = 0.f;
    #pragma unroll
    for (int d = 0; d < 64; d++) s += acc[d];
    float mu = s * (1.0f / 64.0f);
    float var = 0.f;
    #pragma unroll
    for (int d = 0; d < 64; d++) { float a = acc[d] - mu; var += a * a; }
    float inv = 1.0f / sqrtf(var * (1.0f / 64.0f) + 1e-5f);
    #pragma unroll
    for (int d = 0; d < 64; d++) rB[d] = (acc[d] - mu) * inv * sS[256 + d] + sS[320 + d];

    // facc = h1 + b2 ; then += relu(hn2@W1+b1) @ W2 in 4 chunks of 32
    float facc[64];
    #pragma unroll
    for (int j = 0; j < 64; j++) facc[j] = acc[j] + sS[192 + j];

    #pragma unroll
    for (int ch = 0; ch < 4; ch++) {
        float mc[32];
        #pragma unroll
        for (int c = 0; c < 32; c++) mc[c] = sS[64 + ch * 32 + c];
        #pragma unroll 4
        for (int d = 0; d < 64; d++) {
            float a = rB[d];
            const float4* w = (const float4*)&sW1[d * 128 + ch * 32];
            #pragma unroll
            for (int c4 = 0; c4 < 8; c4++) {
                float4 ww = w[c4];
                mc[c4*4+0] += a * ww.x; mc[c4*4+1] += a * ww.y;
                mc[c4*4+2] += a * ww.z; mc[c4*4+3] += a * ww.w;
            }
        }
        #pragma unroll
        for (int c = 0; c < 32; c++) {
            float mm = fmaxf(mc[c], 0.0f);
            const float4* w = (const float4*)&sW2[(ch * 32 + c) * 64];
            #pragma unroll
            for (int j4 = 0; j4 < 16; j4++) {
                float4 ww = w[j4];
                facc[j4*4+0] += mm * ww.x; facc[j4*4+1] += mm * ww.y;
                facc[j4*4+2] += mm * ww.z; facc[j4*4+3] += mm * ww.w;
            }
        }
    }

    float4* op = (float4*)&out[n * 64];
    #pragma unroll
    for (int j4 = 0; j4 < 16; j4++) op[j4] = make_float4(facc[j4*4], facc[j4*4+1], facc[j4*4+2], facc[j4*4+3]);
}

// ---------------- launch ----------------
extern "C" void kernel_launch(void* const* d_in, const int* in_sizes, int n_in,
                              void* d_out, int out_size)
{
    const float* x    = (const float*)d_in[0];
    const int*   ei   = (const int*)  d_in[1];
    const float* ea   = (const float*)d_in[2];
    const float* Wq   = (const float*)d_in[3];
    const float* bq   = (const float*)d_in[4];
    const float* Wk   = (const float*)d_in[5];
    const float* bk   = (const float*)d_in[6];
    const float* Wv   = (const float*)d_in[7];
    const float* bv   = (const float*)d_in[8];
    const float* We   = (const float*)d_in[9];
    const float* be   = (const float*)d_in[10];
    const float* Wo   = (const float*)d_in[11];
    const float* bo   = (const float*)d_in[12];
    const float* edge_w = (const float*)d_in[13];
    const float* msg_w  = (const float*)d_in[14];
    const float* skip   = (const float*)d_in[15];
    const float* ln1g = (const float*)d_in[16];
    const float* ln1b = (const float*)d_in[17];
    const float* lneg = (const float*)d_in[18];
    const float* lneb = (const float*)d_in[19];
    const float* ln2g = (const float*)d_in[20];
    const float* ln2b = (const float*)d_in[21];
    const float* W1   = (const float*)d_in[22];
    const float* b1   = (const float*)d_in[23];
    const float* W2   = (const float*)d_in[24];
    const float* b2   = (const float*)d_in[25];
    const float* attn_bi = (const float*)d_in[26];
    float* out = (float*)d_out;

    size_t sm1 = (size_t)(3 * 4096 + 2 * 1024 + 320 + B1 * 65) * sizeof(float);
    size_t sm2 = (size_t)(4096 + 192 + B2 * 65) * sizeof(float);
    size_t sm4 = (size_t)(4096 + 8192 + 8192 + 384 + 2 * B4 * 65) * sizeof(float);
    cudaFuncSetAttribute(k_node_proj, cudaFuncAttributeMaxDynamicSharedMemorySize, (int)sm1);
    cudaFuncSetAttribute(k_edge,      cudaFuncAttributeMaxDynamicSharedMemorySize, (int)sm2);
    cudaFuncSetAttribute(k_final,     cudaFuncAttributeMaxDynamicSharedMemorySize, (int)sm4);

    // CSR build (int atomics only)
    k_zero_cnt<<<NN / 256, 256>>>();
    k_count<<<EE / 256, 256>>>(ei);
    k_scan<<<1, 1024>>>();
    k_scatter<<<EE / 256, 256>>>(ei);

    // main pipeline
    k_node_proj<<<NN / B1, B1, sm1>>>(x, Wq, bq, Wk, bk, Wv, bv, edge_w, msg_w, ln1g, ln1b);
    k_edge<<<EE / B2, B2, sm2>>>(ea, ei, We, be, lneg, lneb, attn_bi);
    k_attn<<<(NN * 32) / 256, 256>>>(ei);
    k_final<<<NN / B4, B4, sm4>>>(x, Wo, bo, skip, ln2g, ln2b, W1, b1, W2, b2, out);
}

// round 2
// speedup vs baseline: 1.0660x; 1.0660x over previous
#include <cuda_runtime.h>
#include <math.h>

#define NN  65536
#define EE  524288
#define DHD 64
#define NH  4
#define HD  16

typedef unsigned long long u64;

__device__ __forceinline__ u64 pk(float x, float y) {
    u64 r; asm("mov.b64 %0,{%1,%2};" : "=l"(r) : "f"(x), "f"(y)); return r;
}
__device__ __forceinline__ float2 upk(u64 v) {
    float2 f; asm("mov.b64 {%0,%1},%2;" : "=f"(f.x), "=f"(f.y) : "l"(v)); return f;
}
__device__ __forceinline__ void fma2(u64& a, u64 b, u64 c) {
    asm("fma.rn.f32x2 %0,%1,%2,%0;" : "+l"(a) : "l"(b), "l"(c));
}

// ---------------- scratch ----------------
__device__ float g_q[NN * DHD];
__device__ float g_k[NN * DHD];
__device__ float g_v[NN * DHD];
__device__ float g_attn[NN * DHD];
__device__ float g_score[EE * NH];
__device__ int   g_cnt[NN];
__device__ int   g_cur[NN];
__device__ int   g_rs[NN + 1];
__device__ int   g_elist[EE];

// ---------------- CSR build ----------------
__global__ void k_zero_cnt() {
    int i = blockIdx.x * blockDim.x + threadIdx.x;
    if (i < NN) g_cnt[i] = 0;
}
__global__ void k_count(const int* __restrict__ ei) {
    int e = blockIdx.x * blockDim.x + threadIdx.x;
    if (e < EE) atomicAdd(&g_cnt[ei[EE + e]], 1);
}
__global__ void k_scan() {
    __shared__ int sb[1024];
    int t = threadIdx.x;
    int base = t * 64;
    int s = 0;
    for (int j = 0; j < 64; j++) s += g_cnt[base + j];
    sb[t] = s;
    __syncthreads();
    for (int off = 1; off < 1024; off <<= 1) {
        int v = (t >= off) ? sb[t - off] : 0;
        __syncthreads();
        sb[t] += v;
        __syncthreads();
    }
    int run = sb[t] - s;
    for (int j = 0; j < 64; j++) {
        g_rs[base + j]  = run;
        g_cur[base + j] = run;
        run += g_cnt[base + j];
    }
    if (t == 1023) g_rs[NN] = run;
}
__global__ void k_scatter(const int* __restrict__ ei) {
    int e = blockIdx.x * blockDim.x + threadIdx.x;
    if (e < EE) {
        int d = ei[EE + e];
        int p = atomicAdd(&g_cur[d], 1);
        g_elist[p] = e;
    }
}

// ---------------- K1: node LN + QKV + rotations (f32x2) ----------------
#define B1 256
__global__ __launch_bounds__(B1) void k_node_proj(
    const float* __restrict__ x,
    const float* __restrict__ Wq, const float* __restrict__ bq,
    const float* __restrict__ Wk, const float* __restrict__ bk,
    const float* __restrict__ Wv, const float* __restrict__ bv,
    const float* __restrict__ edge_w, const float* __restrict__ msg_w,
    const float* __restrict__ ln1g, const float* __restrict__ ln1b)
{
    extern __shared__ float sm[];
    float* sWq = sm;               // 4096
    float* sWk = sWq + 4096;       // 4096
    float* sWv = sWk + 4096;       // 4096
    float* sEW = sWv + 4096;       // 1024
    float* sMW = sEW + 1024;       // 1024
    float* sB  = sMW + 1024;       // 320
    float* tile = sB + 320;        // B1*65

    int t = threadIdx.x;
    for (int i = t; i < 4096; i += B1) { sWq[i] = Wq[i]; sWk[i] = Wk[i]; sWv[i] = Wv[i]; }
    for (int i = t; i < 1024; i += B1) { sEW[i] = edge_w[i]; sMW[i] = msg_w[i]; }
    if (t < 64) { sB[t] = bq[t]; sB[64+t] = bk[t]; sB[128+t] = bv[t]; sB[192+t] = ln1g[t]; sB[256+t] = ln1b[t]; }
    int nb = blockIdx.x * B1;
    for (int i = t; i < B1 * 64; i += B1) {
        int r = i >> 6, c = i & 63;
        tile[r * 65 + c] = x[(nb + r) * 64 + c];
    }
    __syncthreads();

    float* row = &tile[t * 65];
    float s = 0.f;
    #pragma unroll
    for (int d = 0; d < 64; d++) s += row[d];
    float mu = s * (1.0f / 64.0f);
    float var = 0.f;
    #pragma unroll
    for (int d = 0; d < 64; d++) { float a = row[d] - mu; var += a * a; }
    float inv = 1.0f / sqrtf(var * (1.0f / 64.0f) + 1e-5f);
    #pragma unroll
    for (int d = 0; d < 64; d++) row[d] = (row[d] - mu) * inv * sB[192 + d] + sB[256 + d];

    int n = nb + t;
    u64 acc[32];

    // ---- Q ----
    #pragma unroll
    for (int c = 0; c < 32; c++) acc[c] = pk(sB[2*c], sB[2*c+1]);
    #pragma unroll 4
    for (int d = 0; d < 64; d++) {
        u64 a2 = pk(row[d], row[d]);
        const ulonglong2* w = (const ulonglong2*)&sWq[d * 64];
        #pragma unroll
        for (int c4 = 0; c4 < 16; c4++) {
            ulonglong2 ww = w[c4];
            fma2(acc[2*c4],   a2, ww.x);
            fma2(acc[2*c4+1], a2, ww.y);
        }
    }
    {
        ulonglong2* o = (ulonglong2*)&g_q[n * 64];
        #pragma unroll
        for (int c = 0; c < 16; c++) o[c] = make_ulonglong2(acc[2*c], acc[2*c+1]);
    }

    // ---- K then edge_w rotation ----
    #pragma unroll
    for (int c = 0; c < 32; c++) acc[c] = pk(sB[64+2*c], sB[64+2*c+1]);
    #pragma unroll 4
    for (int d = 0; d < 64; d++) {
        u64 a2 = pk(row[d], row[d]);
        const ulonglong2* w = (const ulonglong2*)&sWk[d * 64];
        #pragma unroll
        for (int c4 = 0; c4 < 16; c4++) {
            ulonglong2 ww = w[c4];
            fma2(acc[2*c4],   a2, ww.x);
            fma2(acc[2*c4+1], a2, ww.y);
        }
    }
    {
        float kv[64];
        #pragma unroll
        for (int c = 0; c < 32; c++) { float2 f = upk(acc[c]); kv[2*c] = f.x; kv[2*c+1] = f.y; }
        #pragma unroll
        for (int h = 0; h < NH; h++) {
            u64 r2[8];
            #pragma unroll
            for (int j = 0; j < 8; j++) r2[j] = 0ULL;
            #pragma unroll
            for (int d2 = 0; d2 < 16; d2++) {
                u64 a2 = pk(kv[h*16 + d2], kv[h*16 + d2]);
                const ulonglong2* w = (const ulonglong2*)&sEW[h*256 + d2*16];
                #pragma unroll
                for (int c4 = 0; c4 < 4; c4++) {
                    ulonglong2 ww = w[c4];
                    fma2(r2[2*c4],   a2, ww.x);
                    fma2(r2[2*c4+1], a2, ww.y);
                }
            }
            ulonglong2* o = (ulonglong2*)&g_k[n * 64 + h * 16];
            #pragma unroll
            for (int c = 0; c < 4; c++) o[c] = make_ulonglong2(r2[2*c], r2[2*c+1]);
        }
    }

    // ---- V then msg_w rotation ----
    #pragma unroll
    for (int c = 0; c < 32; c++) acc[c] = pk(sB[128+2*c], sB[128+2*c+1]);
    #pragma unroll 4
    for (int d = 0; d < 64; d++) {
        u64 a2 = pk(row[d], row[d]);
        const ulonglong2* w = (const ulonglong2*)&sWv[d * 64];
        #pragma unroll
        for (int c4 = 0; c4 < 16; c4++) {
            ulonglong2 ww = w[c4];
            fma2(acc[2*c4],   a2, ww.x);
            fma2(acc[2*c4+1], a2, ww.y);
        }
    }
    {
        float vv[64];
        #pragma unroll
        for (int c = 0; c < 32; c++) { float2 f = upk(acc[c]); vv[2*c] = f.x; vv[2*c+1] = f.y; }
        #pragma unroll
        for (int h = 0; h < NH; h++) {
            u64 r2[8];
            #pragma unroll
            for (int j = 0; j < 8; j++) r2[j] = 0ULL;
            #pragma unroll
            for (int d2 = 0; d2 < 16; d2++) {
                u64 a2 = pk(vv[h*16 + d2], vv[h*16 + d2]);
                const ulonglong2* w = (const ulonglong2*)&sMW[h*256 + d2*16];
                #pragma unroll
                for (int c4 = 0; c4 < 4; c4++) {
                    ulonglong2 ww = w[c4];
                    fma2(r2[2*c4],   a2, ww.x);
                    fma2(r2[2*c4+1], a2, ww.y);
                }
            }
            ulonglong2* o = (ulonglong2*)&g_v[n * 64 + h * 16];
            #pragma unroll
            for (int c = 0; c < 4; c++) o[c] = make_ulonglong2(r2[2*c], r2[2*c+1]);
        }
    }
}

// ---------------- K2: per-edge LN + e projection + scores (f32x2) ----------------
#define B2 256
__global__ __launch_bounds__(B2) void k_edge(
    const float* __restrict__ ea,
    const int*   __restrict__ ei,
    const float* __restrict__ We, const float* __restrict__ be,
    const float* __restrict__ lneg, const float* __restrict__ lneb,
    const float* __restrict__ attn_bi)
{
    extern __shared__ float sm[];
    float* sW = sm;            // 4096
    float* sS = sW + 4096;     // 192
    float* tile = sS + 192;    // B2*65

    int t = threadIdx.x;
    for (int i = t; i < 4096; i += B2) sW[i] = We[i];
    if (t < 64) { sS[t] = be[t]; sS[64 + t] = lneg[t]; sS[128 + t] = lneb[t]; }
    int eb = blockIdx.x * B2;
    for (int i = t; i < B2 * 64; i += B2) {
        int r = i >> 6, c = i & 63;
        tile[r * 65 + c] = ea[(eb + r) * 64 + c];
    }
    __syncthreads();

    float* row = &tile[t * 65];
    float s = 0.f;
    #pragma unroll
    for (int d = 0; d < 64; d++) s += row[d];
    float mu = s * (1.0f / 64.0f);
    float var = 0.f;
    #pragma unroll
    for (int d = 0; d < 64; d++) { float a = row[d] - mu; var += a * a; }
    float inv = 1.0f / sqrtf(var * (1.0f / 64.0f) + 1e-5f);
    #pragma unroll
    for (int d = 0; d < 64; d++) row[d] = (row[d] - mu) * inv * sS[64 + d] + sS[128 + d];

    u64 acc[32];
    #pragma unroll
    for (int c = 0; c < 32; c++) acc[c] = pk(sS[2*c], sS[2*c+1]);
    #pragma unroll 4
    for (int d = 0; d < 64; d++) {
        u64 a2 = pk(row[d], row[d]);
        const ulonglong2* w = (const ulonglong2*)&sW[d * 64];
        #pragma unroll
        for (int c4 = 0; c4 < 16; c4++) {
            ulonglong2 ww = w[c4];
            fma2(acc[2*c4],   a2, ww.x);
            fma2(acc[2*c4+1], a2, ww.y);
        }
    }
    float ev[64];
    #pragma unroll
    for (int c = 0; c < 32; c++) { float2 f = upk(acc[c]); ev[2*c] = f.x; ev[2*c+1] = f.y; }

    int e   = eb + t;
    int src = ei[e];
    int dst = ei[EE + e];
    float sc[4];
    #pragma unroll
    for (int h = 0; h < NH; h++) {
        const float4* qp = (const float4*)&g_q[dst * 64 + h * 16];
        const float4* kp = (const float4*)&g_k[src * 64 + h * 16];
        float dot = 0.f;
        #pragma unroll
        for (int i4 = 0; i4 < 4; i4++) {
            float4 q4 = qp[i4];
            float4 k4 = kp[i4];
            int cb = h * 16 + i4 * 4;
            dot += q4.x * k4.x * ev[cb+0];
            dot += q4.y * k4.y * ev[cb+1];
            dot += q4.z * k4.z * ev[cb+2];
            dot += q4.w * k4.w * ev[cb+3];
        }
        sc[h] = dot * 0.25f + attn_bi[h * 2];
    }
    ((float4*)&g_score[e * 4])[0] = make_float4(sc[0], sc[1], sc[2], sc[3]);
}

// ---------------- K3: segment softmax + weighted gather ----------------
__global__ __launch_bounds__(256) void k_attn(const int* __restrict__ ei)
{
    int gw   = (blockIdx.x * blockDim.x + threadIdx.x) >> 5;
    int lane = threadIdx.x & 31;
    if (gw >= NN) return;
    int start = g_rs[gw], end = g_rs[gw + 1];

    const float NEG = __int_as_float(0xff800000);
    float m0 = NEG, m1 = NEG, m2 = NEG, m3 = NEG;
    for (int i = start + lane; i < end; i += 32) {
        float4 sc = ((const float4*)&g_score[g_elist[i] * 4])[0];
        m0 = fmaxf(m0, sc.x); m1 = fmaxf(m1, sc.y);
        m2 = fmaxf(m2, sc.z); m3 = fmaxf(m3, sc.w);
    }
    #pragma unroll
    for (int o = 16; o; o >>= 1) {
        m0 = fmaxf(m0, __shfl_xor_sync(0xffffffffu, m0, o));
        m1 = fmaxf(m1, __shfl_xor_sync(0xffffffffu, m1, o));
        m2 = fmaxf(m2, __shfl_xor_sync(0xffffffffu, m2, o));
        m3 = fmaxf(m3, __shfl_xor_sync(0xffffffffu, m3, o));
    }
    float s0 = 0.f, s1 = 0.f, s2 = 0.f, s3 = 0.f;
    for (int i = start + lane; i < end; i += 32) {
        float4 sc = ((const float4*)&g_score[g_elist[i] * 4])[0];
        s0 += __expf(sc.x - m0); s1 += __expf(sc.y - m1);
        s2 += __expf(sc.z - m2); s3 += __expf(sc.w - m3);
    }
    #pragma unroll
    for (int o = 16; o; o >>= 1) {
        s0 += __shfl_xor_sync(0xffffffffu, s0, o);
        s1 += __shfl_xor_sync(0xffffffffu, s1, o);
        s2 += __shfl_xor_sync(0xffffffffu, s2, o);
        s3 += __shfl_xor_sync(0xffffffffu, s3, o);
    }

    int   h0  = lane >> 4;
    float mh0 = h0 ? m1 : m0;
    float mh1 = h0 ? m3 : m2;
    float a0 = 0.f, a1 = 0.f;
    for (int i = start; i < end; i++) {
        int e   = g_elist[i];
        int src = ei[e];
        float w0 = __expf(g_score[e * 4 + h0]     - mh0);
        float w1 = __expf(g_score[e * 4 + 2 + h0] - mh1);
        a0 += w0 * g_v[src * 64 + lane];
        a1 += w1 * g_v[src * 64 + 32 + lane];
    }
    float d0 = (h0 ? s1 : s0) + 1e-16f;
    float d1 = (h0 ? s3 : s2) + 1e-16f;
    g_attn[gw * 64 + lane]      = a0 / d0;
    g_attn[gw * 64 + 32 + lane] = a1 / d1;
}

// ---------------- K4: Wo + gated residual + FFN (f32x2, single tile) ----------------
#define B4 256
__global__ __launch_bounds__(B4) void k_final(
    const float* __restrict__ x,
    const float* __restrict__ Wo, const float* __restrict__ bo,
    const float* __restrict__ skip,
    const float* __restrict__ ln2g, const float* __restrict__ ln2b,
    const float* __restrict__ W1, const float* __restrict__ b1,
    const float* __restrict__ W2, const float* __restrict__ b2,
    float* __restrict__ out)
{
    extern __shared__ float sm[];
    float* sWo = sm;               // 4096
    float* sW1 = sWo + 4096;       // 8192
    float* sW2 = sW1 + 8192;       // 8192
    float* sS  = sW2 + 8192;       // 384
    float* tA  = sS + 384;         // B4*65 (reused: attn in -> hn2)

    int t = threadIdx.x;
    for (int i = t; i < 4096; i += B4) sWo[i] = Wo[i];
    for (int i = t; i < 8192; i += B4) { sW1[i] = W1[i]; sW2[i] = W2[i]; }
    if (t < 64)  { sS[t] = bo[t]; sS[192 + t] = b2[t]; sS[256 + t] = ln2g[t]; sS[320 + t] = ln2b[t]; }
    if (t < 128) sS[64 + t] = b1[t];
    int nb = blockIdx.x * B4;
    for (int i = t; i < B4 * 64; i += B4) {
        int r = i >> 6, c = i & 63;
        tA[r * 65 + c] = g_attn[(nb + r) * 64 + c];
    }
    __syncthreads();

    int n = nb + t;
    float* row = &tA[t * 65];

    // o = attn @ Wo + bo
    u64 acc2[32];
    #pragma unroll
    for (int c = 0; c < 32; c++) acc2[c] = pk(sS[2*c], sS[2*c+1]);
    #pragma unroll 4
    for (int d = 0; d < 64; d++) {
        u64 a2 = pk(row[d], row[d]);
        const ulonglong2* w = (const ulonglong2*)&sWo[d * 64];
        #pragma unroll
        for (int c4 = 0; c4 < 16; c4++) {
            ulonglong2 ww = w[c4];
            fma2(acc2[2*c4],   a2, ww.x);
            fma2(acc2[2*c4+1], a2, ww.y);
        }
    }
    float acc[64];
    #pragma unroll
    for (int c = 0; c < 32; c++) { float2 f = upk(acc2[c]); acc[2*c] = f.x; acc[2*c+1] = f.y; }

    // gated residual
    float gg = 1.0f / (1.0f + __expf(-skip[0]));
    const float4* xp = (const float4*)&x[n * 64];
    #pragma unroll
    for (int c4 = 0; c4 < 16; c4++) {
        float4 xx = xp[c4];
        acc[c4*4+0] = gg * acc[c4*4+0] + (1.0f - gg) * xx.x;
        acc[c4*4+1] = gg * acc[c4*4+1] + (1.0f - gg) * xx.y;
        acc[c4*4+2] = gg * acc[c4*4+2] + (1.0f - gg) * xx.z;
        acc[c4*4+3] = gg * acc[c4*4+3] + (1.0f - gg) * xx.w;
    }

    // LN(h1) -> write into tA row (rA is dead now)
    float s = 0.f;
    #pragma unroll
    for (int d = 0; d < 64; d++) s += acc[d];
    float mu = s * (1.0f / 64.0f);
    float var = 0.f;
    #pragma unroll
    for (int d = 0; d < 64; d++) { float a = acc[d] - mu; var += a * a; }
    float inv = 1.0f / sqrtf(var * (1.0f / 64.0f) + 1e-5f);
    __syncthreads();   // everyone done reading rA before overwrite (same row per thread, but keep ordered)
    #pragma unroll
    for (int d = 0; d < 64; d++) row[d] = (acc[d] - mu) * inv * sS[256 + d] + sS[320 + d];

    // facc = h1 + b2 (packed), then += relu(hn2@W1+b1) @ W2
    u64 facc[32];
    #pragma unroll
    for (int j = 0; j < 32; j++) facc[j] = pk(acc[2*j] + sS[192 + 2*j], acc[2*j+1] + sS[192 + 2*j+1]);

    #pragma unroll
    for (int ch = 0; ch < 4; ch++) {
        u64 mc[16];
        #pragma unroll
        for (int c = 0; c < 16; c++) mc[c] = pk(sS[64 + ch*32 + 2*c], sS[64 + ch*32 + 2*c+1]);
        #pragma unroll 4
        for (int d = 0; d < 64; d++) {
            u64 a2 = pk(row[d], row[d]);
            const ulonglong2* w = (const ulonglong2*)&sW1[d * 128 + ch * 32];
            #pragma unroll
            for (int c4 = 0; c4 < 8; c4++) {
                ulonglong2 ww = w[c4];
                fma2(mc[2*c4],   a2, ww.x);
                fma2(mc[2*c4+1], a2, ww.y);
            }
        }
        #pragma unroll
        for (int c = 0; c < 16; c++) {
            float2 m2f = upk(mc[c]);
            float mA = fmaxf(m2f.x, 0.0f);
            float mB = fmaxf(m2f.y, 0.0f);
            {
                u64 a2 = pk(mA, mA);
                const ulonglong2* w = (const ulonglong2*)&sW2[(ch*32 + 2*c) * 64];
                #pragma unroll
                for (int j4 = 0; j4 < 16; j4++) {
                    ulonglong2 ww = w[j4];
                    fma2(facc[2*j4],   a2, ww.x);
                    fma2(facc[2*j4+1], a2, ww.y);
                }
            }
            {
                u64 a2 = pk(mB, mB);
                const ulonglong2* w = (const ulonglong2*)&sW2[(ch*32 + 2*c + 1) * 64];
                #pragma unroll
                for (int j4 = 0; j4 < 16; j4++) {
                    ulonglong2 ww = w[j4];
                    fma2(facc[2*j4],   a2, ww.x);
                    fma2(facc[2*j4+1], a2, ww.y);
                }
            }
        }
    }

    ulonglong2* op = (ulonglong2*)&out[n * 64];
    #pragma unroll
    for (int j = 0; j < 16; j++) op[j] = make_ulonglong2(facc[2*j], facc[2*j+1]);
}

// ---------------- launch ----------------
extern "C" void kernel_launch(void* const* d_in, const int* in_sizes, int n_in,
                              void* d_out, int out_size)
{
    const float* x    = (const float*)d_in[0];
    const int*   ei   = (const int*)  d_in[1];
    const float* ea   = (const float*)d_in[2];
    const float* Wq   = (const float*)d_in[3];
    const float* bq   = (const float*)d_in[4];
    const float* Wk   = (const float*)d_in[5];
    const float* bk   = (const float*)d_in[6];
    const float* Wv   = (const float*)d_in[7];
    const float* bv   = (const float*)d_in[8];
    const float* We   = (const float*)d_in[9];
    const float* be   = (const float*)d_in[10];
    const float* Wo   = (const float*)d_in[11];
    const float* bo   = (const float*)d_in[12];
    const float* edge_w = (const float*)d_in[13];
    const float* msg_w  = (const float*)d_in[14];
    const float* skip   = (const float*)d_in[15];
    const float* ln1g = (const float*)d_in[16];
    const float* ln1b = (const float*)d_in[17];
    const float* lneg = (const float*)d_in[18];
    const float* lneb = (const float*)d_in[19];
    const float* ln2g = (const float*)d_in[20];
    const float* ln2b = (const float*)d_in[21];
    const float* W1   = (const float*)d_in[22];
    const float* b1   = (const float*)d_in[23];
    const float* W2   = (const float*)d_in[24];
    const float* b2   = (const float*)d_in[25];
    const float* attn_bi = (const float*)d_in[26];
    float* out = (float*)d_out;

    size_t sm1 = (size_t)(3 * 4096 + 2 * 1024 + 320 + B1 * 65) * sizeof(float);
    size_t sm2 = (size_t)(4096 + 192 + B2 * 65) * sizeof(float);
    size_t sm4 = (size_t)(4096 + 8192 + 8192 + 384 + B4 * 65) * sizeof(float);
    cudaFuncSetAttribute(k_node_proj, cudaFuncAttributeMaxDynamicSharedMemorySize, (int)sm1);
    cudaFuncSetAttribute(k_edge,      cudaFuncAttributeMaxDynamicSharedMemorySize, (int)sm2);
    cudaFuncSetAttribute(k_final,     cudaFuncAttributeMaxDynamicSharedMemorySize, (int)sm4);

    k_zero_cnt<<<NN / 256, 256>>>();
    k_count<<<EE / 256, 256>>>(ei);
    k_scan<<<1, 1024>>>();
    k_scatter<<<EE / 256, 256>>>(ei);

    k_node_proj<<<NN / B1, B1, sm1>>>(x, Wq, bq, Wk, bk, Wv, bv, edge_w, msg_w, ln1g, ln1b);
    k_edge<<<EE / B2, B2, sm2>>>(ea, ei, We, be, lneg, lneb, attn_bi);
    k_attn<<<(NN * 32) / 256, 256>>>(ei);
    k_final<<<NN / B4, B4, sm4>>>(x, Wo, bo, skip, ln2g, ln2b, W1, b1, W2, b2, out);
}